// round 2
// baseline (speedup 1.0000x reference)
#include <cuda_runtime.h>
#include <stdint.h>
#include <math.h>

#define B_ 4
#define N_ 4
#define C_ 256
#define H_ 100
#define W_ 152
#define HW_ (H_*W_)

// Scratch (device globals: no allocations allowed)
__device__ float g_S   [B_*(N_+1)*HW_];   // per-pixel channel sums, m = b*5 + t (t=0 feat, 1..4 nearby)
__device__ float g_avg [B_*(N_+1)*HW_];   // 3x3 box averages
__device__ int   g_mism[B_*N_*HW_];       // mismatch counts (sim = 2304 - mism)
__device__ float g_fused[(size_t)B_*C_*HW_]; // fused activations [b][c][hw]

// ---------------------------------------------------------------------------
// K1: per-pixel channel sum, sequential ascending c (bit-exact association)
// ---------------------------------------------------------------------------
__global__ __launch_bounds__(256) void sum_kernel(const float* __restrict__ feat,
                                                  const float* __restrict__ nearby) {
    int p = blockIdx.x * blockDim.x + threadIdx.x;
    int m = blockIdx.y;                  // 0..19
    if (p >= HW_) return;
    int b = m / (N_+1), t = m % (N_+1);
    const float* src = (t == 0) ? (feat + (size_t)b * C_ * HW_)
                                : (nearby + (size_t)(b * N_ + (t-1)) * C_ * HW_);
    float acc = 0.0f;
    #pragma unroll 1
    for (int c0 = 0; c0 < C_; c0 += 8) {
        float v[8];
        #pragma unroll
        for (int k = 0; k < 8; k++) v[k] = src[(size_t)(c0 + k) * HW_ + p];
        // sequential adds on one accumulator: order must match reference
        #pragma unroll
        for (int k = 0; k < 8; k++) acc += v[k];
    }
    g_S[(size_t)m * HW_ + p] = acc;
}

// ---------------------------------------------------------------------------
// K2: 3x3 edge-clamped box average, add order = (di,dj) row-major (reference order)
// ---------------------------------------------------------------------------
__global__ __launch_bounds__(256) void avg_kernel() {
    int p = blockIdx.x * blockDim.x + threadIdx.x;
    int m = blockIdx.y;
    if (p >= HW_) return;
    int i = p / W_, j = p % W_;
    const float* S = g_S + (size_t)m * HW_;
    float acc = 0.0f;
    #pragma unroll
    for (int di = 0; di < 3; di++) {
        int y = min(max(i + di - 1, 0), H_ - 1);
        #pragma unroll
        for (int dj = 0; dj < 3; dj++) {
            int x = min(max(j + dj - 1, 0), W_ - 1);
            acc += S[y * W_ + x];
        }
    }
    g_avg[(size_t)m * HW_ + p] = acc * (1.0f / 2304.0f);  // fp32(1/(9*256)), correctly rounded
}

// ---------------------------------------------------------------------------
// K3: census mismatch counts. Tile 32x8 centers + halo in smem, loop channels.
// match(a>=T1, b>=T2) via sign-bit XOR of fp32 differences (exact).
// ---------------------------------------------------------------------------
#define TW 32
#define TH 8
#define TILE_LD (5 * (TH+2) * (TW+2))   // 1700 floats per channel step

__global__ __launch_bounds__(256) void sim_kernel(const float* __restrict__ feat,
                                                  const float* __restrict__ nearby) {
    __shared__ float sm[5][TH+2][TW+2];
    float* smf = &sm[0][0][0];

    int tid = threadIdx.x;
    int tx = tid % TW;
    int ty = tid / TW;
    int j0 = blockIdx.x * TW, i0 = blockIdx.y * TH;
    int b  = blockIdx.z;
    int i = i0 + ty, j = j0 + tx;
    bool valid = (i < H_) && (j < W_);
    int p = i * W_ + j;

    float T1 = 0.0f, T2[N_] = {0,0,0,0};
    if (valid) {
        T1 = g_avg[(size_t)(b*(N_+1) + 0) * HW_ + p];
        #pragma unroll
        for (int n = 0; n < N_; n++)
            T2[n] = g_avg[(size_t)(b*(N_+1) + 1 + n) * HW_ + p];
    }

    // Precompute per-slot gmem pointers for the cooperative tile load
    const float* fbase = feat   + (size_t)b * C_ * HW_;
    const float* nbase = nearby + (size_t)b * N_ * C_ * HW_;
    const float* lptr[7];
    #pragma unroll
    for (int q = 0; q < 7; q++) {
        int idx = tid + q * 256;
        if (idx < TILE_LD) {
            int t = idx / ((TH+2)*(TW+2));
            int r = idx % ((TH+2)*(TW+2));
            int y = r / (TW+2), x = r % (TW+2);
            int gy = min(max(i0 + y - 1, 0), H_ - 1);
            int gx = min(max(j0 + x - 1, 0), W_ - 1);
            const float* src = (t == 0) ? fbase : (nbase + (size_t)(t-1) * C_ * HW_);
            lptr[q] = src + gy * W_ + gx;
        } else {
            lptr[q] = nullptr;
        }
    }

    int mism[N_] = {0,0,0,0};

    for (int c = 0; c < C_; c++) {
        __syncthreads();
        #pragma unroll
        for (int q = 0; q < 7; q++) {
            int idx = tid + q * 256;
            if (idx < TILE_LD) smf[idx] = lptr[q][(size_t)c * HW_];
        }
        __syncthreads();

        unsigned u1[9];
        #pragma unroll
        for (int k = 0; k < 9; k++) {
            int dy = k / 3, dx = k % 3;
            u1[k] = __float_as_uint(sm[0][ty+dy][tx+dx] - T1);
        }
        #pragma unroll
        for (int n = 0; n < N_; n++) {
            int acc = 0;
            #pragma unroll
            for (int k = 0; k < 9; k++) {
                int dy = k / 3, dx = k % 3;
                unsigned u2 = __float_as_uint(sm[1+n][ty+dy][tx+dx] - T2[n]);
                acc += (int)((u1[k] ^ u2) >> 31);
            }
            mism[n] += acc;
        }
    }

    if (valid) {
        #pragma unroll
        for (int n = 0; n < N_; n++)
            g_mism[(size_t)(b * N_ + n) * HW_ + p] = mism[n];
    }
}

// ---------------------------------------------------------------------------
// K4: softmax over n (softmax(sim) == softmax(-mism)) + weighted fuse + residual
// ---------------------------------------------------------------------------
__global__ __launch_bounds__(256) void fuse_kernel(const float* __restrict__ feat,
                                                   const float* __restrict__ nearby) {
    int p = blockIdx.x * blockDim.x + threadIdx.x;
    int b = blockIdx.y;
    if (p >= HW_) return;

    int m0 = g_mism[(size_t)(b*N_+0)*HW_ + p];
    int m1 = g_mism[(size_t)(b*N_+1)*HW_ + p];
    int m2 = g_mism[(size_t)(b*N_+2)*HW_ + p];
    int m3 = g_mism[(size_t)(b*N_+3)*HW_ + p];
    int mn = min(min(m0, m1), min(m2, m3));
    float e0 = expf((float)(mn - m0));
    float e1 = expf((float)(mn - m1));
    float e2 = expf((float)(mn - m2));
    float e3 = expf((float)(mn - m3));
    float s = e0 + e1 + e2 + e3;
    float w0 = e0 / s, w1 = e1 / s, w2 = e2 / s, w3 = e3 / s;

    const float* f0 = feat   + (size_t)b * C_ * HW_ + p;
    const float* n0 = nearby + (size_t)(b*N_+0) * C_ * HW_ + p;
    const float* n1 = nearby + (size_t)(b*N_+1) * C_ * HW_ + p;
    const float* n2 = nearby + (size_t)(b*N_+2) * C_ * HW_ + p;
    const float* n3 = nearby + (size_t)(b*N_+3) * C_ * HW_ + p;
    float* dst = g_fused + (size_t)b * C_ * HW_ + p;

    #pragma unroll 4
    for (int c = 0; c < C_; c++) {
        size_t off = (size_t)c * HW_;
        float v = w0 * n0[off];
        v = fmaf(w1, n1[off], v);
        v = fmaf(w2, n2[off], v);
        v = fmaf(w3, n3[off], v);
        v += f0[off];
        dst[off] = v;
    }
}

// ---------------------------------------------------------------------------
// K5: fp32 SGEMM  out[b][o][p] = sum_c W[o][c] * fused[b][c][p] + bias[o]
// 128x128x8 tiles, 8x8 per thread, 256 threads
// ---------------------------------------------------------------------------
__global__ __launch_bounds__(256) void gemm_kernel(const float* __restrict__ Wf,
                                                   const float* __restrict__ bias,
                                                   float* __restrict__ out) {
    const int BM = 128, BN = 128, BK = 8;
    __shared__ float As[BK][BM];
    __shared__ float Bs[BK][BN];

    int b  = blockIdx.z;
    int o0 = blockIdx.y * BM;
    int p0 = blockIdx.x * BN;
    int tid = threadIdx.x;
    int trow = tid / 16, tcol = tid % 16;

    const float* Bbase = g_fused + (size_t)b * C_ * HW_;

    int arow = tid / 2,  acol = (tid % 2) * 4;   // A: [128 o][8 c] tile, one float4/thread
    int brow = tid / 32, bcol = (tid % 32) * 4;  // B: [8 c][128 p] tile, one float4/thread
    bool fullN = (p0 + BN <= HW_);

    float acc[8][8];
    #pragma unroll
    for (int i = 0; i < 8; i++)
        #pragma unroll
        for (int j = 0; j < 8; j++) acc[i][j] = 0.0f;

    for (int c0 = 0; c0 < C_; c0 += BK) {
        float4 av = *(const float4*)(Wf + (size_t)(o0 + arow) * C_ + c0 + acol);
        float4 bv;
        if (fullN) {
            bv = *(const float4*)(Bbase + (size_t)(c0 + brow) * HW_ + p0 + bcol);
        } else {
            const float* r = Bbase + (size_t)(c0 + brow) * HW_;
            bv.x = (p0 + bcol + 0 < HW_) ? r[p0 + bcol + 0] : 0.0f;
            bv.y = (p0 + bcol + 1 < HW_) ? r[p0 + bcol + 1] : 0.0f;
            bv.z = (p0 + bcol + 2 < HW_) ? r[p0 + bcol + 2] : 0.0f;
            bv.w = (p0 + bcol + 3 < HW_) ? r[p0 + bcol + 3] : 0.0f;
        }
        __syncthreads();
        As[acol + 0][arow] = av.x;
        As[acol + 1][arow] = av.y;
        As[acol + 2][arow] = av.z;
        As[acol + 3][arow] = av.w;
        *(float4*)&Bs[brow][bcol] = bv;
        __syncthreads();

        #pragma unroll
        for (int k = 0; k < BK; k++) {
            float4 a0 = *(const float4*)&As[k][trow * 8];
            float4 a1 = *(const float4*)&As[k][trow * 8 + 4];
            float4 b0 = *(const float4*)&Bs[k][tcol * 8];
            float4 b1 = *(const float4*)&Bs[k][tcol * 8 + 4];
            float af[8] = {a0.x, a0.y, a0.z, a0.w, a1.x, a1.y, a1.z, a1.w};
            float bf[8] = {b0.x, b0.y, b0.z, b0.w, b1.x, b1.y, b1.z, b1.w};
            #pragma unroll
            for (int i = 0; i < 8; i++)
                #pragma unroll
                for (int j = 0; j < 8; j++)
                    acc[i][j] = fmaf(af[i], bf[j], acc[i][j]);
        }
    }

    #pragma unroll
    for (int i = 0; i < 8; i++) {
        int o = o0 + trow * 8 + i;
        float bv = bias[o];
        float* orow = out + ((size_t)b * C_ + o) * HW_ + p0;
        #pragma unroll
        for (int j = 0; j < 8; j++) {
            int pl = tcol * 8 + j;
            if (p0 + pl < HW_) orow[pl] = acc[i][j] + bv;
        }
    }
}

// ---------------------------------------------------------------------------
extern "C" void kernel_launch(void* const* d_in, const int* in_sizes, int n_in,
                              void* d_out, int out_size) {
    const float* feat   = (const float*)d_in[0];
    const float* nearby = (const float*)d_in[1];
    const float* wf     = (const float*)d_in[2];
    const float* bf     = (const float*)d_in[3];
    float* out = (float*)d_out;

    dim3 g1((HW_ + 255) / 256, B_ * (N_ + 1));
    sum_kernel<<<g1, 256>>>(feat, nearby);
    avg_kernel<<<g1, 256>>>();

    dim3 g3((W_ + TW - 1) / TW, (H_ + TH - 1) / TH, B_);
    sim_kernel<<<g3, 256>>>(feat, nearby);

    dim3 g4((HW_ + 255) / 256, B_);
    fuse_kernel<<<g4, 256>>>(feat, nearby);

    dim3 g5((HW_ + 127) / 128, C_ / 128, B_);
    gemm_kernel<<<g5, 256>>>(wf, bf, out);
}

// round 8
// speedup vs baseline: 1.3698x; 1.3698x over previous
#include <cuda_runtime.h>
#include <cuda_bf16.h>
#include <stdint.h>
#include <math.h>

#define B_ 4
#define N_ 4
#define C_ 256
#define H_ 100
#define W_ 152
#define HW_ (H_*W_)
#define PPAD 15360           // 120 tiles of 128 px

// ---------------- device scratch (no allocations allowed) ----------------
__device__ float g_S   [B_*(N_+1)*HW_];
__device__ float g_avg [B_*(N_+1)*HW_];
__device__ int   g_mism[B_*N_*HW_];
__device__ __nv_bfloat16 g_whi[C_*C_];
__device__ __nv_bfloat16 g_wlo[C_*C_];
__device__ __nv_bfloat16 g_fhiT[(size_t)B_*PPAD*C_];   // fused^T hi [b][p][c]
__device__ __nv_bfloat16 g_floT[(size_t)B_*PPAD*C_];   // fused^T lo [b][p][c]

__device__ __forceinline__ uint32_t smem_u32(const void* p) {
    uint32_t a;
    asm("{ .reg .u64 t; cvta.to.shared.u64 t, %1; cvt.u32.u64 %0, t; }" : "=r"(a) : "l"(p));
    return a;
}
#define CP_ASYNC16(dst, src) \
    asm volatile("cp.async.cg.shared.global [%0], [%1], 16;" :: "r"(dst), "l"(src))
#define CP_COMMIT() asm volatile("cp.async.commit_group;" ::: "memory")
#define CP_WAIT(n)  asm volatile("cp.async.wait_group %0;" :: "n"(n) : "memory")

__device__ __forceinline__ void mma16816(float* d, const uint32_t* a, const uint32_t* b) {
    asm volatile("mma.sync.aligned.m16n8k16.row.col.f32.bf16.bf16.f32 "
        "{%0,%1,%2,%3}, {%4,%5,%6,%7}, {%8,%9}, {%0,%1,%2,%3};"
        : "+f"(d[0]), "+f"(d[1]), "+f"(d[2]), "+f"(d[3])
        : "r"(a[0]), "r"(a[1]), "r"(a[2]), "r"(a[3]), "r"(b[0]), "r"(b[1]));
}

// ---------------------------------------------------------------------------
// K0: split W into bf16 hi/lo
// ---------------------------------------------------------------------------
__global__ __launch_bounds__(256) void wprep_kernel(const float* __restrict__ w) {
    int i = blockIdx.x * 256 + threadIdx.x;
    float v = w[i];
    __nv_bfloat16 hi = __float2bfloat16(v);
    g_whi[i] = hi;
    g_wlo[i] = __float2bfloat16(v - __bfloat162float(hi));
}

// ---------------------------------------------------------------------------
// K1: per-pixel channel sum, sequential ascending c (bit-exact association)
// ---------------------------------------------------------------------------
__global__ __launch_bounds__(256) void sum_kernel(const float* __restrict__ feat,
                                                  const float* __restrict__ nearby) {
    int p = blockIdx.x * blockDim.x + threadIdx.x;
    int m = blockIdx.y;
    if (p >= HW_) return;
    int b = m / (N_+1), t = m % (N_+1);
    const float* src = (t == 0) ? (feat + (size_t)b * C_ * HW_)
                                : (nearby + (size_t)(b * N_ + (t-1)) * C_ * HW_);
    float acc = 0.0f;
    #pragma unroll 1
    for (int c0 = 0; c0 < C_; c0 += 8) {
        float v[8];
        #pragma unroll
        for (int k = 0; k < 8; k++) v[k] = src[(size_t)(c0 + k) * HW_ + p];
        #pragma unroll
        for (int k = 0; k < 8; k++) acc += v[k];
    }
    g_S[(size_t)m * HW_ + p] = acc;
}

// ---------------------------------------------------------------------------
// K2: 3x3 edge-clamped box average, (di,dj) row-major add order
// ---------------------------------------------------------------------------
__global__ __launch_bounds__(256) void avg_kernel() {
    int p = blockIdx.x * blockDim.x + threadIdx.x;
    int m = blockIdx.y;
    if (p >= HW_) return;
    int i = p / W_, j = p % W_;
    const float* S = g_S + (size_t)m * HW_;
    float acc = 0.0f;
    #pragma unroll
    for (int di = 0; di < 3; di++) {
        int y = min(max(i + di - 1, 0), H_ - 1);
        #pragma unroll
        for (int dj = 0; dj < 3; dj++) {
            int x = min(max(j + dj - 1, 0), W_ - 1);
            acc += S[y * W_ + x];
        }
    }
    g_avg[(size_t)m * HW_ + p] = acc * (1.0f / 2304.0f);
}

// ---------------------------------------------------------------------------
// K3: census mismatch counts (sign-bit XOR trick)
// ---------------------------------------------------------------------------
#define TW 32
#define TH 8
#define TILE_LD (5 * (TH+2) * (TW+2))

__global__ __launch_bounds__(256) void sim_kernel(const float* __restrict__ feat,
                                                  const float* __restrict__ nearby) {
    __shared__ float sm[5][TH+2][TW+2];
    float* smf = &sm[0][0][0];

    int tid = threadIdx.x;
    int tx = tid % TW;
    int ty = tid / TW;
    int j0 = blockIdx.x * TW, i0 = blockIdx.y * TH;
    int b  = blockIdx.z;
    int i = i0 + ty, j = j0 + tx;
    bool valid = (i < H_) && (j < W_);
    int p = i * W_ + j;

    float T1 = 0.0f, T2[N_] = {0,0,0,0};
    if (valid) {
        T1 = g_avg[(size_t)(b*(N_+1) + 0) * HW_ + p];
        #pragma unroll
        for (int n = 0; n < N_; n++)
            T2[n] = g_avg[(size_t)(b*(N_+1) + 1 + n) * HW_ + p];
    }

    const float* fbase = feat   + (size_t)b * C_ * HW_;
    const float* nbase = nearby + (size_t)b * N_ * C_ * HW_;
    const float* lptr[7];
    #pragma unroll
    for (int q = 0; q < 7; q++) {
        int idx = tid + q * 256;
        if (idx < TILE_LD) {
            int t = idx / ((TH+2)*(TW+2));
            int r = idx % ((TH+2)*(TW+2));
            int y = r / (TW+2), x = r % (TW+2);
            int gy = min(max(i0 + y - 1, 0), H_ - 1);
            int gx = min(max(j0 + x - 1, 0), W_ - 1);
            const float* src = (t == 0) ? fbase : (nbase + (size_t)(t-1) * C_ * HW_);
            lptr[q] = src + gy * W_ + gx;
        } else {
            lptr[q] = nullptr;
        }
    }

    int mism[N_] = {0,0,0,0};

    for (int c = 0; c < C_; c++) {
        __syncthreads();
        #pragma unroll
        for (int q = 0; q < 7; q++) {
            int idx = tid + q * 256;
            if (idx < TILE_LD) smf[idx] = lptr[q][(size_t)c * HW_];
        }
        __syncthreads();

        unsigned u1[9];
        #pragma unroll
        for (int k = 0; k < 9; k++) {
            int dy = k / 3, dx = k % 3;
            u1[k] = __float_as_uint(sm[0][ty+dy][tx+dx] - T1);
        }
        #pragma unroll
        for (int n = 0; n < N_; n++) {
            int acc = 0;
            #pragma unroll
            for (int k = 0; k < 9; k++) {
                int dy = k / 3, dx = k % 3;
                unsigned u2 = __float_as_uint(sm[1+n][ty+dy][tx+dx] - T2[n]);
                acc += (int)((u1[k] ^ u2) >> 31);
            }
            mism[n] += acc;
        }
    }

    if (valid) {
        #pragma unroll
        for (int n = 0; n < N_; n++)
            g_mism[(size_t)(b * N_ + n) * HW_ + p] = mism[n];
    }
}

// ---------------------------------------------------------------------------
// K4: softmax + weighted fuse; writes bf16 hi/lo TRANSPOSED [b][p][c]
// ---------------------------------------------------------------------------
__global__ __launch_bounds__(256) void fuse_kernel(const float* __restrict__ feat,
                                                   const float* __restrict__ nearby) {
    __shared__ float4 w_s[32];
    __shared__ __nv_bfloat16 s_hi[32][258];
    __shared__ __nv_bfloat16 s_lo[32][258];

    int tid = threadIdx.x;
    int b = blockIdx.y;
    int p0 = blockIdx.x * 32;

    if (tid < 32) {
        int p = p0 + tid;
        int m0 = g_mism[(size_t)(b*N_+0)*HW_ + p];
        int m1 = g_mism[(size_t)(b*N_+1)*HW_ + p];
        int m2 = g_mism[(size_t)(b*N_+2)*HW_ + p];
        int m3 = g_mism[(size_t)(b*N_+3)*HW_ + p];
        int mn = min(min(m0, m1), min(m2, m3));
        float e0 = expf((float)(mn - m0));
        float e1 = expf((float)(mn - m1));
        float e2 = expf((float)(mn - m2));
        float e3 = expf((float)(mn - m3));
        float s = e0 + e1 + e2 + e3;
        w_s[tid] = make_float4(e0 / s, e1 / s, e2 / s, e3 / s);
    }
    __syncthreads();

    int c   = tid >> 3;
    int px0 = (tid & 7) * 4;
    const float* fp = feat   + (size_t)b * C_ * HW_ + p0 + px0;
    const float* np = nearby + (size_t)b * N_ * C_ * HW_ + p0 + px0;
    float4 wv[4] = {w_s[px0], w_s[px0+1], w_s[px0+2], w_s[px0+3]};

    #pragma unroll
    for (int cc = 0; cc < 8; cc++) {
        int cg = cc * 32 + c;
        size_t co = (size_t)cg * HW_;
        float4 fv = *(const float4*)(fp + co);
        float4 a0 = *(const float4*)(np + co);
        float4 a1 = *(const float4*)(np + (size_t)C_ * HW_ + co);
        float4 a2 = *(const float4*)(np + (size_t)2 * C_ * HW_ + co);
        float4 a3 = *(const float4*)(np + (size_t)3 * C_ * HW_ + co);
        float fr[4] = {fv.x, fv.y, fv.z, fv.w};
        float r0[4] = {a0.x, a0.y, a0.z, a0.w};
        float r1[4] = {a1.x, a1.y, a1.z, a1.w};
        float r2[4] = {a2.x, a2.y, a2.z, a2.w};
        float r3[4] = {a3.x, a3.y, a3.z, a3.w};
        #pragma unroll
        for (int e = 0; e < 4; e++) {
            float4 w = wv[e];
            float v = w.x * r0[e];
            v = fmaf(w.y, r1[e], v);
            v = fmaf(w.z, r2[e], v);
            v = fmaf(w.w, r3[e], v);
            v += fr[e];
            __nv_bfloat16 hi = __float2bfloat16(v);
            s_hi[px0 + e][cg] = hi;
            s_lo[px0 + e][cg] = __float2bfloat16(v - __bfloat162float(hi));
        }
    }
    __syncthreads();

    uint32_t* dh = (uint32_t*)g_fhiT + ((size_t)b * PPAD + p0) * (C_/2);
    uint32_t* dl = (uint32_t*)g_floT + ((size_t)b * PPAD + p0) * (C_/2);
    #pragma unroll
    for (int q = 0; q < 16; q++) {
        int w = tid + q * 256;
        int row = w >> 7, cw = w & 127;
        dh[(size_t)row * 128 + cw] = *(const uint32_t*)&s_hi[row][cw * 2];
        dl[(size_t)row * 128 + cw] = *(const uint32_t*)&s_lo[row][cw * 2];
    }
}

// ---------------------------------------------------------------------------
// K5: mma.sync bf16 split GEMM.  out[b][o][p] = sum_c W[o][c]*F[c][p] + bias[o]
// CTA: M=128(o) x N=128(p), K_eff=768 in 12 chunks of 64, cp.async 2-stage.
// 8 warps as 2(M) x 4(N); warp tile 64x32; fragments via direct LDS.32.
// smem row pitch = 72 bf16 (144B: 16B-multiple, conflict-free frag loads)
// ---------------------------------------------------------------------------
#define WPITCH 36                       // 32-bit words per smem row
#define ST_A   18432                    // 128*144 bytes
#define STAGE  36864                    // A + B per stage
#define GEMM_SMEM (2*STAGE)             // 73728

__global__ __launch_bounds__(256, 2)
void gemm_kernel(const float* __restrict__ bias, float* __restrict__ out) {
    extern __shared__ char smem[];
    uint32_t sb = smem_u32(smem);

    int tid = threadIdx.x, wid = tid >> 5, lid = tid & 31;
    int g = lid >> 2, t = lid & 3;
    int wm = wid & 1, wn = wid >> 1;
    int p0 = blockIdx.x * 128, o0 = blockIdx.y * 128, b = blockIdx.z;

    int ldrow = tid >> 3, ldcol = tid & 7;      // 16B-chunk loader coords

    float acc[4][4][4];
    #pragma unroll
    for (int i = 0; i < 4; i++)
        #pragma unroll
        for (int j = 0; j < 4; j++)
            #pragma unroll
            for (int k = 0; k < 4; k++) acc[i][j][k] = 0.0f;

    // ---- chunk loader ----
    auto load_chunk = [&](int kk) {
        int buf = kk & 1, seg = kk >> 2, cc0 = (kk & 3) * 64;
        const __nv_bfloat16* As = (seg < 2) ? g_whi : g_wlo;
        const __nv_bfloat16* Bs = (seg == 1) ? g_floT : g_fhiT;
        uint32_t da = sb + buf * STAGE;
        uint32_t db = da + ST_A;
        const __nv_bfloat16* ga = As + (size_t)(o0 + ldrow) * C_ + cc0 + ldcol * 8;
        const __nv_bfloat16* gb = Bs + ((size_t)b * PPAD + p0 + ldrow) * C_ + cc0 + ldcol * 8;
        #pragma unroll
        for (int q = 0; q < 4; q++) {       // 32 rows per q-step
            CP_ASYNC16(da + (ldrow + q*32) * 144 + ldcol * 16, ga + (size_t)(q*32) * C_);
            CP_ASYNC16(db + (ldrow + q*32) * 144 + ldcol * 16, gb + (size_t)(q*32) * C_);
        }
        CP_COMMIT();
    };

    load_chunk(0);

    for (int kk = 0; kk < 12; kk++) {
        if (kk + 1 < 12) { load_chunk(kk + 1); CP_WAIT(1); }
        else             { CP_WAIT(0); }
        __syncthreads();

        const uint32_t* Aw = (const uint32_t*)(smem + (kk & 1) * STAGE);
        const uint32_t* Bw = (const uint32_t*)(smem + (kk & 1) * STAGE + ST_A);

        #pragma unroll
        for (int s = 0; s < 4; s++) {       // 4 x k16
            uint32_t afr[4][4];
            #pragma unroll
            for (int mf = 0; mf < 4; mf++) {
                int r = wm * 64 + mf * 16 + g;
                afr[mf][0] = Aw[(r    ) * WPITCH + s*8     + t];
                afr[mf][1] = Aw[(r + 8) * WPITCH + s*8     + t];
                afr[mf][2] = Aw[(r    ) * WPITCH + s*8 + 4 + t];
                afr[mf][3] = Aw[(r + 8) * WPITCH + s*8 + 4 + t];
            }
            uint32_t bfr[4][2];
            #pragma unroll
            for (int nf = 0; nf < 4; nf++) {
                int r = wn * 32 + nf * 8 + g;
                bfr[nf][0] = Bw[r * WPITCH + s*8     + t];
                bfr[nf][1] = Bw[r * WPITCH + s*8 + 4 + t];
            }
            #pragma unroll
            for (int mf = 0; mf < 4; mf++)
                #pragma unroll
                for (int nf = 0; nf < 4; nf++)
                    mma16816(acc[mf][nf], afr[mf], bfr[nf]);
        }
        __syncthreads();
    }

    // ---- epilogue: direct float2 stores + bias ----
    #pragma unroll
    for (int mf = 0; mf < 4; mf++) {
        int o  = o0 + wm * 64 + mf * 16 + g;
        float bv0 = bias[o];
        float bv1 = bias[o + 8];
        float* r0 = out + ((size_t)b * C_ + o    ) * HW_;
        float* r1 = out + ((size_t)b * C_ + o + 8) * HW_;
        #pragma unroll
        for (int nf = 0; nf < 4; nf++) {
            int p = p0 + wn * 32 + nf * 8 + 2 * t;
            if (p < HW_) {
                *(float2*)(r0 + p) = make_float2(acc[mf][nf][0] + bv0, acc[mf][nf][1] + bv0);
                *(float2*)(r1 + p) = make_float2(acc[mf][nf][2] + bv1, acc[mf][nf][3] + bv1);
            }
        }
    }
}

// ---------------------------------------------------------------------------
extern "C" void kernel_launch(void* const* d_in, const int* in_sizes, int n_in,
                              void* d_out, int out_size) {
    const float* feat   = (const float*)d_in[0];
    const float* nearby = (const float*)d_in[1];
    const float* wf     = (const float*)d_in[2];
    const float* bf     = (const float*)d_in[3];
    float* out = (float*)d_out;

    cudaFuncSetAttribute(gemm_kernel, cudaFuncAttributeMaxDynamicSharedMemorySize, GEMM_SMEM);

    wprep_kernel<<<C_*C_/256, 256>>>(wf);

    dim3 g1((HW_ + 255) / 256, B_ * (N_ + 1));
    sum_kernel<<<g1, 256>>>(feat, nearby);
    avg_kernel<<<g1, 256>>>();

    dim3 g3((W_ + TW - 1) / TW, (H_ + TH - 1) / TH, B_);
    sim_kernel<<<g3, 256>>>(feat, nearby);

    dim3 g4(HW_ / 32, B_);
    fuse_kernel<<<g4, 256>>>(feat, nearby);

    dim3 g5(PPAD / 128, C_ / 128, B_);
    gemm_kernel<<<g5, 256, GEMM_SMEM>>>(bf, out);
}

// round 9
// speedup vs baseline: 1.6353x; 1.1939x over previous
#include <cuda_runtime.h>
#include <cuda_bf16.h>
#include <stdint.h>
#include <math.h>

#define B_ 4
#define N_ 4
#define C_ 256
#define H_ 100
#define W_ 152
#define HW_ (H_*W_)
#define PPAD 15360           // 120 tiles of 128 px

// ---------------- device scratch (no allocations allowed) ----------------
__device__ float g_S   [B_*(N_+1)*HW_];
__device__ float g_avg [B_*(N_+1)*HW_];
__device__ int   g_mism[B_*N_*HW_];
__device__ __nv_bfloat16 g_whi[C_*C_];
__device__ __nv_bfloat16 g_wlo[C_*C_];
__device__ __nv_bfloat16 g_fhiT[(size_t)B_*PPAD*C_];   // fused^T hi [b][p][c]
__device__ __nv_bfloat16 g_floT[(size_t)B_*PPAD*C_];   // fused^T lo [b][p][c]

__device__ __forceinline__ uint32_t smem_u32(const void* p) {
    uint32_t a;
    asm("{ .reg .u64 t; cvta.to.shared.u64 t, %1; cvt.u32.u64 %0, t; }" : "=r"(a) : "l"(p));
    return a;
}
#define CP_ASYNC16(dst, src) \
    asm volatile("cp.async.cg.shared.global [%0], [%1], 16;" :: "r"(dst), "l"(src))
#define CP_ASYNC4(dst, src) \
    asm volatile("cp.async.ca.shared.global [%0], [%1], 4;" :: "r"(dst), "l"(src))
#define CP_COMMIT() asm volatile("cp.async.commit_group;" ::: "memory")
#define CP_WAIT(n)  asm volatile("cp.async.wait_group %0;" :: "n"(n) : "memory")

__device__ __forceinline__ void mma16816(float* d, const uint32_t* a, const uint32_t* b) {
    asm volatile("mma.sync.aligned.m16n8k16.row.col.f32.bf16.bf16.f32 "
        "{%0,%1,%2,%3}, {%4,%5,%6,%7}, {%8,%9}, {%0,%1,%2,%3};"
        : "+f"(d[0]), "+f"(d[1]), "+f"(d[2]), "+f"(d[3])
        : "r"(a[0]), "r"(a[1]), "r"(a[2]), "r"(a[3]), "r"(b[0]), "r"(b[1]));
}

// ---------------------------------------------------------------------------
// K0: split W into bf16 hi/lo
// ---------------------------------------------------------------------------
__global__ __launch_bounds__(256) void wprep_kernel(const float* __restrict__ w) {
    int i = blockIdx.x * 256 + threadIdx.x;
    float v = w[i];
    __nv_bfloat16 hi = __float2bfloat16(v);
    g_whi[i] = hi;
    g_wlo[i] = __float2bfloat16(v - __bfloat162float(hi));
}

// zero mismatch accumulators (graph replays must be deterministic)
__global__ __launch_bounds__(256) void zero_mism() {
    int i = blockIdx.x * 256 + threadIdx.x;
    if (i < B_*N_*HW_) g_mism[i] = 0;
}

// ---------------------------------------------------------------------------
// K1: per-pixel channel sum, sequential ascending c (bit-exact association)
// ---------------------------------------------------------------------------
__global__ __launch_bounds__(256) void sum_kernel(const float* __restrict__ feat,
                                                  const float* __restrict__ nearby) {
    int p = blockIdx.x * blockDim.x + threadIdx.x;
    int m = blockIdx.y;
    if (p >= HW_) return;
    int b = m / (N_+1), t = m % (N_+1);
    const float* src = (t == 0) ? (feat + (size_t)b * C_ * HW_)
                                : (nearby + (size_t)(b * N_ + (t-1)) * C_ * HW_);
    float acc = 0.0f;
    #pragma unroll 1
    for (int c0 = 0; c0 < C_; c0 += 8) {
        float v[8];
        #pragma unroll
        for (int k = 0; k < 8; k++) v[k] = src[(size_t)(c0 + k) * HW_ + p];
        #pragma unroll
        for (int k = 0; k < 8; k++) acc += v[k];
    }
    g_S[(size_t)m * HW_ + p] = acc;
}

// ---------------------------------------------------------------------------
// K2: 3x3 edge-clamped box average, (di,dj) row-major add order
// ---------------------------------------------------------------------------
__global__ __launch_bounds__(256) void avg_kernel() {
    int p = blockIdx.x * blockDim.x + threadIdx.x;
    int m = blockIdx.y;
    if (p >= HW_) return;
    int i = p / W_, j = p % W_;
    const float* S = g_S + (size_t)m * HW_;
    float acc = 0.0f;
    #pragma unroll
    for (int di = 0; di < 3; di++) {
        int y = min(max(i + di - 1, 0), H_ - 1);
        #pragma unroll
        for (int dj = 0; dj < 3; dj++) {
            int x = min(max(j + dj - 1, 0), W_ - 1);
            acc += S[y * W_ + x];
        }
    }
    g_avg[(size_t)m * HW_ + p] = acc * (1.0f / 2304.0f);
}

// ---------------------------------------------------------------------------
// K3: census mismatch counts (sign-bit XOR trick)
// channel-split grid (8 chunks of 32) + 3-stage cp.async ring, 1 barrier/chan
// ---------------------------------------------------------------------------
#define TW 32
#define TH 8
#define PLANE ((TH+2)*(TW+2))          // 340
#define TILE_LD (5 * PLANE)            // 1700 floats per channel
#define CHUNK 32

__global__ __launch_bounds__(256) void sim_kernel(const float* __restrict__ feat,
                                                  const float* __restrict__ nearby) {
    __shared__ float sm[3][TILE_LD];   // 20.4 KB ring

    int tid = threadIdx.x;
    int tx = tid % TW;
    int ty = tid / TW;
    int j0 = blockIdx.x * TW, i0 = blockIdx.y * TH;
    int bz = blockIdx.z;
    int b  = bz >> 3;
    int c0 = (bz & 7) * CHUNK;
    int i = i0 + ty, j = j0 + tx;
    bool valid = (i < H_) && (j < W_);
    int p = i * W_ + j;

    float T1 = 0.0f, T2[N_] = {0,0,0,0};
    if (valid) {
        T1 = g_avg[(size_t)(b*(N_+1) + 0) * HW_ + p];
        #pragma unroll
        for (int n = 0; n < N_; n++)
            T2[n] = g_avg[(size_t)(b*(N_+1) + 1 + n) * HW_ + p];
    }

    // per-slot gmem pointers + smem byte offsets for the cooperative load
    const float* fbase = feat   + (size_t)b * C_ * HW_ + (size_t)c0 * HW_;
    const float* nbase = nearby + (size_t)b * N_ * C_ * HW_ + (size_t)c0 * HW_;
    const float* lptr[7];
    uint32_t sdst[7];
    uint32_t smbase = smem_u32(&sm[0][0]);
    #pragma unroll
    for (int q = 0; q < 7; q++) {
        int idx = tid + q * 256;
        if (idx < TILE_LD) {
            int t = idx / PLANE;
            int r = idx % PLANE;
            int y = r / (TW+2), x = r % (TW+2);
            int gy = min(max(i0 + y - 1, 0), H_ - 1);
            int gx = min(max(j0 + x - 1, 0), W_ - 1);
            const float* src = (t == 0) ? fbase : (nbase + (size_t)(t-1) * C_ * HW_);
            lptr[q] = src + gy * W_ + gx;
            sdst[q] = smbase + (uint32_t)idx * 4u;
        } else {
            lptr[q] = nullptr;
            sdst[q] = 0;
        }
    }
    bool q6 = (tid + 6*256) < TILE_LD;

    // prefetch channels 0 and 1
    #pragma unroll
    for (int s = 0; s < 2; s++) {
        uint32_t soff = (uint32_t)s * (TILE_LD * 4u);
        #pragma unroll
        for (int q = 0; q < 6; q++) CP_ASYNC4(sdst[q] + soff, lptr[q] + (size_t)s * HW_);
        if (q6) CP_ASYNC4(sdst[6] + soff, lptr[6] + (size_t)s * HW_);
        CP_COMMIT();
    }

    int mism[N_] = {0,0,0,0};

    #pragma unroll 1
    for (int c = 0; c < CHUNK; c++) {
        CP_WAIT(1);
        __syncthreads();        // data for c arrived; everyone done reading slot (c+2)%3

        // prefetch channel c+2 into the slot just freed
        if (c + 2 < CHUNK) {
            uint32_t soff = (uint32_t)((c + 2) % 3) * (TILE_LD * 4u);
            size_t goff = (size_t)(c + 2) * HW_;
            #pragma unroll
            for (int q = 0; q < 6; q++) CP_ASYNC4(sdst[q] + soff, lptr[q] + goff);
            if (q6) CP_ASYNC4(sdst[6] + soff, lptr[6] + goff);
        }
        CP_COMMIT();            // empty groups at tail keep wait counts consistent

        const float* smc = &sm[c % 3][0];
        unsigned u1[9];
        #pragma unroll
        for (int k = 0; k < 9; k++) {
            int dy = k / 3, dx = k % 3;
            u1[k] = __float_as_uint(smc[(ty+dy)*(TW+2) + tx+dx] - T1);
        }
        #pragma unroll
        for (int n = 0; n < N_; n++) {
            const float* smn = smc + (1 + n) * PLANE;
            int acc = 0;
            #pragma unroll
            for (int k = 0; k < 9; k++) {
                int dy = k / 3, dx = k % 3;
                unsigned u2 = __float_as_uint(smn[(ty+dy)*(TW+2) + tx+dx] - T2[n]);
                acc += (int)((u1[k] ^ u2) >> 31);
            }
            mism[n] += acc;
        }
    }

    if (valid) {
        #pragma unroll
        for (int n = 0; n < N_; n++)
            atomicAdd(&g_mism[(size_t)(b * N_ + n) * HW_ + p], mism[n]);
    }
}

// ---------------------------------------------------------------------------
// K4: softmax + weighted fuse; writes bf16 hi/lo TRANSPOSED [b][p][c]
// ---------------------------------------------------------------------------
__global__ __launch_bounds__(256) void fuse_kernel(const float* __restrict__ feat,
                                                   const float* __restrict__ nearby) {
    __shared__ float4 w_s[32];
    __shared__ __nv_bfloat16 s_hi[32][258];
    __shared__ __nv_bfloat16 s_lo[32][258];

    int tid = threadIdx.x;
    int b = blockIdx.y;
    int p0 = blockIdx.x * 32;

    if (tid < 32) {
        int p = p0 + tid;
        int m0 = g_mism[(size_t)(b*N_+0)*HW_ + p];
        int m1 = g_mism[(size_t)(b*N_+1)*HW_ + p];
        int m2 = g_mism[(size_t)(b*N_+2)*HW_ + p];
        int m3 = g_mism[(size_t)(b*N_+3)*HW_ + p];
        int mn = min(min(m0, m1), min(m2, m3));
        float e0 = expf((float)(mn - m0));
        float e1 = expf((float)(mn - m1));
        float e2 = expf((float)(mn - m2));
        float e3 = expf((float)(mn - m3));
        float s = e0 + e1 + e2 + e3;
        w_s[tid] = make_float4(e0 / s, e1 / s, e2 / s, e3 / s);
    }
    __syncthreads();

    int c   = tid >> 3;
    int px0 = (tid & 7) * 4;
    const float* fp = feat   + (size_t)b * C_ * HW_ + p0 + px0;
    const float* np = nearby + (size_t)b * N_ * C_ * HW_ + p0 + px0;
    float4 wv[4] = {w_s[px0], w_s[px0+1], w_s[px0+2], w_s[px0+3]};

    #pragma unroll
    for (int cc = 0; cc < 8; cc++) {
        int cg = cc * 32 + c;
        size_t co = (size_t)cg * HW_;
        float4 fv = *(const float4*)(fp + co);
        float4 a0 = *(const float4*)(np + co);
        float4 a1 = *(const float4*)(np + (size_t)C_ * HW_ + co);
        float4 a2 = *(const float4*)(np + (size_t)2 * C_ * HW_ + co);
        float4 a3 = *(const float4*)(np + (size_t)3 * C_ * HW_ + co);
        float fr[4] = {fv.x, fv.y, fv.z, fv.w};
        float r0[4] = {a0.x, a0.y, a0.z, a0.w};
        float r1[4] = {a1.x, a1.y, a1.z, a1.w};
        float r2[4] = {a2.x, a2.y, a2.z, a2.w};
        float r3[4] = {a3.x, a3.y, a3.z, a3.w};
        #pragma unroll
        for (int e = 0; e < 4; e++) {
            float4 w = wv[e];
            float v = w.x * r0[e];
            v = fmaf(w.y, r1[e], v);
            v = fmaf(w.z, r2[e], v);
            v = fmaf(w.w, r3[e], v);
            v += fr[e];
            __nv_bfloat16 hi = __float2bfloat16(v);
            s_hi[px0 + e][cg] = hi;
            s_lo[px0 + e][cg] = __float2bfloat16(v - __bfloat162float(hi));
        }
    }
    __syncthreads();

    uint32_t* dh = (uint32_t*)g_fhiT + ((size_t)b * PPAD + p0) * (C_/2);
    uint32_t* dl = (uint32_t*)g_floT + ((size_t)b * PPAD + p0) * (C_/2);
    #pragma unroll
    for (int q = 0; q < 16; q++) {
        int w = tid + q * 256;
        int row = w >> 7, cw = w & 127;
        dh[(size_t)row * 128 + cw] = *(const uint32_t*)&s_hi[row][cw * 2];
        dl[(size_t)row * 128 + cw] = *(const uint32_t*)&s_lo[row][cw * 2];
    }
}

// ---------------------------------------------------------------------------
// K5: mma.sync bf16 split GEMM.  out[b][o][p] = sum_c W[o][c]*F[c][p] + bias[o]
// CTA: M=128(o) x N=128(p), K_eff=768 in 12 chunks of 64, cp.async 2-stage.
// ---------------------------------------------------------------------------
#define WPITCH 36                       // 32-bit words per smem row
#define ST_A   18432                    // 128*144 bytes
#define STAGE  36864                    // A + B per stage
#define GEMM_SMEM (2*STAGE)             // 73728

__global__ __launch_bounds__(256, 2)
void gemm_kernel(const float* __restrict__ bias, float* __restrict__ out) {
    extern __shared__ char smem[];
    uint32_t sb = smem_u32(smem);

    int tid = threadIdx.x, wid = tid >> 5, lid = tid & 31;
    int g = lid >> 2, t = lid & 3;
    int wm = wid & 1, wn = wid >> 1;
    int p0 = blockIdx.x * 128, o0 = blockIdx.y * 128, b = blockIdx.z;

    int ldrow = tid >> 3, ldcol = tid & 7;

    float acc[4][4][4];
    #pragma unroll
    for (int i = 0; i < 4; i++)
        #pragma unroll
        for (int j = 0; j < 4; j++)
            #pragma unroll
            for (int k = 0; k < 4; k++) acc[i][j][k] = 0.0f;

    auto load_chunk = [&](int kk) {
        int buf = kk & 1, seg = kk >> 2, cc0 = (kk & 3) * 64;
        const __nv_bfloat16* As = (seg < 2) ? g_whi : g_wlo;
        const __nv_bfloat16* Bs = (seg == 1) ? g_floT : g_fhiT;
        uint32_t da = sb + buf * STAGE;
        uint32_t db = da + ST_A;
        const __nv_bfloat16* ga = As + (size_t)(o0 + ldrow) * C_ + cc0 + ldcol * 8;
        const __nv_bfloat16* gb = Bs + ((size_t)b * PPAD + p0 + ldrow) * C_ + cc0 + ldcol * 8;
        #pragma unroll
        for (int q = 0; q < 4; q++) {
            CP_ASYNC16(da + (ldrow + q*32) * 144 + ldcol * 16, ga + (size_t)(q*32) * C_);
            CP_ASYNC16(db + (ldrow + q*32) * 144 + ldcol * 16, gb + (size_t)(q*32) * C_);
        }
        CP_COMMIT();
    };

    load_chunk(0);

    for (int kk = 0; kk < 12; kk++) {
        if (kk + 1 < 12) { load_chunk(kk + 1); CP_WAIT(1); }
        else             { CP_WAIT(0); }
        __syncthreads();

        const uint32_t* Aw = (const uint32_t*)(smem + (kk & 1) * STAGE);
        const uint32_t* Bw = (const uint32_t*)(smem + (kk & 1) * STAGE + ST_A);

        #pragma unroll
        for (int s = 0; s < 4; s++) {
            uint32_t afr[4][4];
            #pragma unroll
            for (int mf = 0; mf < 4; mf++) {
                int r = wm * 64 + mf * 16 + g;
                afr[mf][0] = Aw[(r    ) * WPITCH + s*8     + t];
                afr[mf][1] = Aw[(r + 8) * WPITCH + s*8     + t];
                afr[mf][2] = Aw[(r    ) * WPITCH + s*8 + 4 + t];
                afr[mf][3] = Aw[(r + 8) * WPITCH + s*8 + 4 + t];
            }
            uint32_t bfr[4][2];
            #pragma unroll
            for (int nf = 0; nf < 4; nf++) {
                int r = wn * 32 + nf * 8 + g;
                bfr[nf][0] = Bw[r * WPITCH + s*8     + t];
                bfr[nf][1] = Bw[r * WPITCH + s*8 + 4 + t];
            }
            #pragma unroll
            for (int mf = 0; mf < 4; mf++)
                #pragma unroll
                for (int nf = 0; nf < 4; nf++)
                    mma16816(acc[mf][nf], afr[mf], bfr[nf]);
        }
        __syncthreads();
    }

    #pragma unroll
    for (int mf = 0; mf < 4; mf++) {
        int o  = o0 + wm * 64 + mf * 16 + g;
        float bv0 = bias[o];
        float bv1 = bias[o + 8];
        float* r0 = out + ((size_t)b * C_ + o    ) * HW_;
        float* r1 = out + ((size_t)b * C_ + o + 8) * HW_;
        #pragma unroll
        for (int nf = 0; nf < 4; nf++) {
            int p = p0 + wn * 32 + nf * 8 + 2 * t;
            if (p < HW_) {
                *(float2*)(r0 + p) = make_float2(acc[mf][nf][0] + bv0, acc[mf][nf][1] + bv0);
                *(float2*)(r1 + p) = make_float2(acc[mf][nf][2] + bv1, acc[mf][nf][3] + bv1);
            }
        }
    }
}

// ---------------------------------------------------------------------------
extern "C" void kernel_launch(void* const* d_in, const int* in_sizes, int n_in,
                              void* d_out, int out_size) {
    const float* feat   = (const float*)d_in[0];
    const float* nearby = (const float*)d_in[1];
    const float* wf     = (const float*)d_in[2];
    const float* bf     = (const float*)d_in[3];
    float* out = (float*)d_out;

    cudaFuncSetAttribute(gemm_kernel, cudaFuncAttributeMaxDynamicSharedMemorySize, GEMM_SMEM);

    wprep_kernel<<<C_*C_/256, 256>>>(wf);
    zero_mism<<<(B_*N_*HW_ + 255)/256, 256>>>();

    dim3 g1((HW_ + 255) / 256, B_ * (N_ + 1));
    sum_kernel<<<g1, 256>>>(feat, nearby);
    avg_kernel<<<g1, 256>>>();

    dim3 g3((W_ + TW - 1) / TW, (H_ + TH - 1) / TH, B_ * 8);
    sim_kernel<<<g3, 256>>>(feat, nearby);

    dim3 g4(HW_ / 32, B_);
    fuse_kernel<<<g4, 256>>>(feat, nearby);

    dim3 g5(PPAD / 128, C_ / 128, B_);
    gemm_kernel<<<g5, 256, GEMM_SMEM>>>(bf, out);
}

// round 11
// speedup vs baseline: 1.8264x; 1.1169x over previous
#include <cuda_runtime.h>
#include <cuda_bf16.h>
#include <stdint.h>
#include <math.h>

#define B_ 4
#define N_ 4
#define C_ 256
#define H_ 100
#define W_ 152
#define HW_ (H_*W_)
#define PPAD 15360           // 120 tiles of 128 px

// ---------------- device scratch (no allocations allowed) ----------------
__device__ float g_S   [B_*(N_+1)*HW_];
__device__ float g_avg [B_*(N_+1)*HW_];
__device__ int   g_mism[B_*N_*HW_];
__device__ __nv_bfloat16 g_whi[C_*C_];
__device__ __nv_bfloat16 g_wlo[C_*C_];
__device__ __nv_bfloat16 g_fhiT[(size_t)B_*PPAD*C_];   // fused^T hi [b][p][c]
__device__ __nv_bfloat16 g_floT[(size_t)B_*PPAD*C_];   // fused^T lo [b][p][c]

__device__ __forceinline__ uint32_t smem_u32(const void* p) {
    uint32_t a;
    asm("{ .reg .u64 t; cvta.to.shared.u64 t, %1; cvt.u32.u64 %0, t; }" : "=r"(a) : "l"(p));
    return a;
}
#define CP_ASYNC16(dst, src) \
    asm volatile("cp.async.cg.shared.global [%0], [%1], 16;" :: "r"(dst), "l"(src))
#define CP_COMMIT() asm volatile("cp.async.commit_group;" ::: "memory")
#define CP_WAIT(n)  asm volatile("cp.async.wait_group %0;" :: "n"(n) : "memory")

__device__ __forceinline__ void mma16816(float* d, const uint32_t* a, const uint32_t* b) {
    asm volatile("mma.sync.aligned.m16n8k16.row.col.f32.bf16.bf16.f32 "
        "{%0,%1,%2,%3}, {%4,%5,%6,%7}, {%8,%9}, {%0,%1,%2,%3};"
        : "+f"(d[0]), "+f"(d[1]), "+f"(d[2]), "+f"(d[3])
        : "r"(a[0]), "r"(a[1]), "r"(a[2]), "r"(a[3]), "r"(b[0]), "r"(b[1]));
}

// ---------------------------------------------------------------------------
// K0: split W into bf16 hi/lo
// ---------------------------------------------------------------------------
__global__ __launch_bounds__(256) void wprep_kernel(const float* __restrict__ w) {
    int i = blockIdx.x * 256 + threadIdx.x;
    float v = w[i];
    __nv_bfloat16 hi = __float2bfloat16(v);
    g_whi[i] = hi;
    g_wlo[i] = __float2bfloat16(v - __bfloat162float(hi));
}

// zero mismatch accumulators (graph replays must be deterministic)
__global__ __launch_bounds__(256) void zero_mism() {
    int i = blockIdx.x * 256 + threadIdx.x;
    if (i < B_*N_*HW_) g_mism[i] = 0;
}

// ---------------------------------------------------------------------------
// K1: per-pixel channel sum, sequential ascending c (bit-exact association)
// ---------------------------------------------------------------------------
__global__ __launch_bounds__(256) void sum_kernel(const float* __restrict__ feat,
                                                  const float* __restrict__ nearby) {
    int p = blockIdx.x * blockDim.x + threadIdx.x;
    int m = blockIdx.y;
    if (p >= HW_) return;
    int b = m / (N_+1), t = m % (N_+1);
    const float* src = (t == 0) ? (feat + (size_t)b * C_ * HW_)
                                : (nearby + (size_t)(b * N_ + (t-1)) * C_ * HW_);
    float acc = 0.0f;
    #pragma unroll 1
    for (int c0 = 0; c0 < C_; c0 += 8) {
        float v[8];
        #pragma unroll
        for (int k = 0; k < 8; k++) v[k] = src[(size_t)(c0 + k) * HW_ + p];
        #pragma unroll
        for (int k = 0; k < 8; k++) acc += v[k];
    }
    g_S[(size_t)m * HW_ + p] = acc;
}

// ---------------------------------------------------------------------------
// K2: 3x3 edge-clamped box average, (di,dj) row-major add order
// ---------------------------------------------------------------------------
__global__ __launch_bounds__(256) void avg_kernel() {
    int p = blockIdx.x * blockDim.x + threadIdx.x;
    int m = blockIdx.y;
    if (p >= HW_) return;
    int i = p / W_, j = p % W_;
    const float* S = g_S + (size_t)m * HW_;
    float acc = 0.0f;
    #pragma unroll
    for (int di = 0; di < 3; di++) {
        int y = min(max(i + di - 1, 0), H_ - 1);
        #pragma unroll
        for (int dj = 0; dj < 3; dj++) {
            int x = min(max(j + dj - 1, 0), W_ - 1);
            acc += S[y * W_ + x];
        }
    }
    g_avg[(size_t)m * HW_ + p] = acc * (1.0f / 2304.0f);
}

// ---------------------------------------------------------------------------
// K3: census mismatch counts (sign-bit XOR trick)
// 2 pixels/thread (32x16 tile), 16B cp.async rows, double-buffer, 1 bar/chan
// ---------------------------------------------------------------------------
#define TW 32
#define TH 16
#define SROW 40                        // floats per smem row (aligned 160B)
#define PROWS 18                       // halo rows per plane
#define PLANEF (PROWS*SROW)            // 720
#define CHF (5*PLANEF)                 // 3600 floats per channel
#define LOADS (5*PROWS*10)             // 900 uint4 per channel
#define CHUNK 32

__global__ __launch_bounds__(256, 3) void sim_kernel(const float* __restrict__ feat,
                                                     const float* __restrict__ nearby) {
    __shared__ float sm[2][CHF];       // 28.8 KB double buffer

    int tid = threadIdx.x;
    int tx = tid & 31;
    int ty = tid >> 5;                 // 0..7
    int j0 = blockIdx.x * TW, i0 = blockIdx.y * TH;
    int bz = blockIdx.z;
    int b  = bz >> 3;
    int c0 = (bz & 7) * CHUNK;
    int iA = i0 + 2*ty, iB = iA + 1;
    int j  = j0 + tx;
    bool vA = (iA < H_) && (j < W_);
    bool vB = (iB < H_) && (j < W_);
    int pA = iA * W_ + j, pB = pA + W_;

    int xlo = max(j0 - 4, 0);
    // smem x-indices for dx = 0,1,2 (edge-clamped like the reference)
    int sx0 = min(max(j - 1, 0), W_-1) - xlo;
    int sx1 = min(max(j    , 0), W_-1) - xlo;
    int sx2 = min(max(j + 1, 0), W_-1) - xlo;

    float T1a = 0.f, T1b = 0.f, T2a[N_] = {0,0,0,0}, T2b[N_] = {0,0,0,0};
    if (vA) {
        T1a = g_avg[(size_t)(b*5 + 0) * HW_ + pA];
        #pragma unroll
        for (int n = 0; n < N_; n++) T2a[n] = g_avg[(size_t)(b*5 + 1 + n) * HW_ + pA];
    }
    if (vB) {
        T1b = g_avg[(size_t)(b*5 + 0) * HW_ + pB];
        #pragma unroll
        for (int n = 0; n < N_; n++) T2b[n] = g_avg[(size_t)(b*5 + 1 + n) * HW_ + pB];
    }

    // cooperative loader: 900 uint4 per channel, 4 slots/thread
    const float* fbase = feat   + ((size_t)b * C_ + c0) * HW_;
    const float* nbase = nearby + ((size_t)(b * N_) * C_ + c0) * HW_;
    const float* lptr[4];
    uint32_t sdst[4];
    uint32_t smbase = smem_u32(&sm[0][0]);
    #pragma unroll
    for (int q = 0; q < 4; q++) {
        int idx = tid + q * 256;
        if (idx < LOADS) {
            int row = idx / 10, ch = idx % 10;
            int t = row / PROWS, r = row % PROWS;
            int gy = min(max(i0 + r - 1, 0), H_ - 1);
            int xs = min(xlo + ch * 4, W_ - 4);      // stay in-plane; extra slots unused
            const float* base = (t == 0) ? fbase : (nbase + (size_t)(t - 1) * C_ * HW_);
            lptr[q] = base + gy * W_ + xs;
            sdst[q] = smbase + (uint32_t)(t * PLANEF + r * SROW + ch * 4) * 4u;
        } else {
            lptr[q] = fbase;   // idx 768..899 only in q=3; guard below
            sdst[q] = smbase;
        }
    }
    bool q3 = (tid + 3*256) < LOADS;

    // prefetch channel 0 into slot 0
    #pragma unroll
    for (int q = 0; q < 3; q++) CP_ASYNC16(sdst[q], lptr[q]);
    if (q3) CP_ASYNC16(sdst[3], lptr[3]);
    CP_COMMIT();

    int mA[N_] = {0,0,0,0}, mB[N_] = {0,0,0,0};

    #pragma unroll 1
    for (int c = 0; c < CHUNK; c++) {
        CP_WAIT(0);
        __syncthreads();               // chan c visible; all done with slot (c+1)&1

        if (c + 1 < CHUNK) {           // prefetch c+1 into the other slot
            uint32_t soff = (uint32_t)((c + 1) & 1) * (CHF * 4u);
            size_t goff = (size_t)(c + 1) * HW_;
            #pragma unroll
            for (int q = 0; q < 3; q++) CP_ASYNC16(sdst[q] + soff, lptr[q] + goff);
            if (q3) CP_ASYNC16(sdst[3] + soff, lptr[3] + goff);
        }
        CP_COMMIT();

        const float* S = &sm[c & 1][0] + (2 * ty) * SROW;

        // feature plane: signs for both pixels
        unsigned uA[9], uB[9];
        {
            float x[4][3];
            #pragma unroll
            for (int rr = 0; rr < 4; rr++) {
                x[rr][0] = S[rr * SROW + sx0];
                x[rr][1] = S[rr * SROW + sx1];
                x[rr][2] = S[rr * SROW + sx2];
            }
            #pragma unroll
            for (int dy = 0; dy < 3; dy++)
                #pragma unroll
                for (int dx = 0; dx < 3; dx++) {
                    uA[dy*3+dx] = __float_as_uint(x[dy  ][dx] - T1a);
                    uB[dy*3+dx] = __float_as_uint(x[dy+1][dx] - T1b);
                }
        }
        #pragma unroll
        for (int n = 0; n < N_; n++) {
            const float* Sn = S + (1 + n) * PLANEF;
            float x[4][3];
            #pragma unroll
            for (int rr = 0; rr < 4; rr++) {
                x[rr][0] = Sn[rr * SROW + sx0];
                x[rr][1] = Sn[rr * SROW + sx1];
                x[rr][2] = Sn[rr * SROW + sx2];
            }
            int aA = 0, aB = 0;
            #pragma unroll
            for (int dy = 0; dy < 3; dy++)
                #pragma unroll
                for (int dx = 0; dx < 3; dx++) {
                    unsigned dA = __float_as_uint(x[dy  ][dx] - T2a[n]);
                    unsigned dB = __float_as_uint(x[dy+1][dx] - T2b[n]);
                    aA += (int)__umulhi(uA[dy*3+dx] ^ dA, 2u);   // IMAD.HI on fma pipe
                    aB += (int)__umulhi(uB[dy*3+dx] ^ dB, 2u);
                }
            mA[n] += aA;
            mB[n] += aB;
        }
    }

    if (vA) {
        #pragma unroll
        for (int n = 0; n < N_; n++)
            atomicAdd(&g_mism[(size_t)(b * N_ + n) * HW_ + pA], mA[n]);
    }
    if (vB) {
        #pragma unroll
        for (int n = 0; n < N_; n++)
            atomicAdd(&g_mism[(size_t)(b * N_ + n) * HW_ + pB], mB[n]);
    }
}

// ---------------------------------------------------------------------------
// K4: softmax + weighted fuse; writes bf16 hi/lo TRANSPOSED [b][p][c]
// ---------------------------------------------------------------------------
__global__ __launch_bounds__(256) void fuse_kernel(const float* __restrict__ feat,
                                                   const float* __restrict__ nearby) {
    __shared__ float4 w_s[32];
    __shared__ __nv_bfloat16 s_hi[32][258];
    __shared__ __nv_bfloat16 s_lo[32][258];

    int tid = threadIdx.x;
    int b = blockIdx.y;
    int p0 = blockIdx.x * 32;

    if (tid < 32) {
        int p = p0 + tid;
        int m0 = g_mism[(size_t)(b*N_+0)*HW_ + p];
        int m1 = g_mism[(size_t)(b*N_+1)*HW_ + p];
        int m2 = g_mism[(size_t)(b*N_+2)*HW_ + p];
        int m3 = g_mism[(size_t)(b*N_+3)*HW_ + p];
        int mn = min(min(m0, m1), min(m2, m3));
        float e0 = expf((float)(mn - m0));
        float e1 = expf((float)(mn - m1));
        float e2 = expf((float)(mn - m2));
        float e3 = expf((float)(mn - m3));
        float s = e0 + e1 + e2 + e3;
        w_s[tid] = make_float4(e0 / s, e1 / s, e2 / s, e3 / s);
    }
    __syncthreads();

    int c   = tid >> 3;
    int px0 = (tid & 7) * 4;
    const float* fp = feat   + (size_t)b * C_ * HW_ + p0 + px0;
    const float* np = nearby + (size_t)b * N_ * C_ * HW_ + p0 + px0;
    float4 wv[4] = {w_s[px0], w_s[px0+1], w_s[px0+2], w_s[px0+3]};

    #pragma unroll
    for (int cc = 0; cc < 8; cc++) {
        int cg = cc * 32 + c;
        size_t co = (size_t)cg * HW_;
        float4 fv = *(const float4*)(fp + co);
        float4 a0 = *(const float4*)(np + co);
        float4 a1 = *(const float4*)(np + (size_t)C_ * HW_ + co);
        float4 a2 = *(const float4*)(np + (size_t)2 * C_ * HW_ + co);
        float4 a3 = *(const float4*)(np + (size_t)3 * C_ * HW_ + co);
        float fr[4] = {fv.x, fv.y, fv.z, fv.w};
        float r0[4] = {a0.x, a0.y, a0.z, a0.w};
        float r1[4] = {a1.x, a1.y, a1.z, a1.w};
        float r2[4] = {a2.x, a2.y, a2.z, a2.w};
        float r3[4] = {a3.x, a3.y, a3.z, a3.w};
        #pragma unroll
        for (int e = 0; e < 4; e++) {
            float4 w = wv[e];
            float v = w.x * r0[e];
            v = fmaf(w.y, r1[e], v);
            v = fmaf(w.z, r2[e], v);
            v = fmaf(w.w, r3[e], v);
            v += fr[e];
            __nv_bfloat16 hi = __float2bfloat16(v);
            s_hi[px0 + e][cg] = hi;
            s_lo[px0 + e][cg] = __float2bfloat16(v - __bfloat162float(hi));
        }
    }
    __syncthreads();

    uint32_t* dh = (uint32_t*)g_fhiT + ((size_t)b * PPAD + p0) * (C_/2);
    uint32_t* dl = (uint32_t*)g_floT + ((size_t)b * PPAD + p0) * (C_/2);
    #pragma unroll
    for (int q = 0; q < 16; q++) {
        int w = tid + q * 256;
        int row = w >> 7, cw = w & 127;
        dh[(size_t)row * 128 + cw] = *(const uint32_t*)&s_hi[row][cw * 2];
        dl[(size_t)row * 128 + cw] = *(const uint32_t*)&s_lo[row][cw * 2];
    }
}

// ---------------------------------------------------------------------------
// K5: mma.sync bf16 split GEMM.  out[b][o][p] = sum_c W[o][c]*F[c][p] + bias[o]
// ---------------------------------------------------------------------------
#define WPITCH 36                       // 32-bit words per smem row
#define ST_A   18432                    // 128*144 bytes
#define STAGE  36864                    // A + B per stage
#define GEMM_SMEM (2*STAGE)             // 73728

__global__ __launch_bounds__(256, 2)
void gemm_kernel(const float* __restrict__ bias, float* __restrict__ out) {
    extern __shared__ char smem[];
    uint32_t sb = smem_u32(smem);

    int tid = threadIdx.x, wid = tid >> 5, lid = tid & 31;
    int g = lid >> 2, t = lid & 3;
    int wm = wid & 1, wn = wid >> 1;
    int p0 = blockIdx.x * 128, o0 = blockIdx.y * 128, b = blockIdx.z;

    int ldrow = tid >> 3, ldcol = tid & 7;

    float acc[4][4][4];
    #pragma unroll
    for (int i = 0; i < 4; i++)
        #pragma unroll
        for (int j = 0; j < 4; j++)
            #pragma unroll
            for (int k = 0; k < 4; k++) acc[i][j][k] = 0.0f;

    auto load_chunk = [&](int kk) {
        int buf = kk & 1, seg = kk >> 2, cc0 = (kk & 3) * 64;
        const __nv_bfloat16* As = (seg < 2) ? g_whi : g_wlo;
        const __nv_bfloat16* Bs = (seg == 1) ? g_floT : g_fhiT;
        uint32_t da = sb + buf * STAGE;
        uint32_t db = da + ST_A;
        const __nv_bfloat16* ga = As + (size_t)(o0 + ldrow) * C_ + cc0 + ldcol * 8;
        const __nv_bfloat16* gb = Bs + ((size_t)b * PPAD + p0 + ldrow) * C_ + cc0 + ldcol * 8;
        #pragma unroll
        for (int q = 0; q < 4; q++) {
            CP_ASYNC16(da + (ldrow + q*32) * 144 + ldcol * 16, ga + (size_t)(q*32) * C_);
            CP_ASYNC16(db + (ldrow + q*32) * 144 + ldcol * 16, gb + (size_t)(q*32) * C_);
        }
        CP_COMMIT();
    };

    load_chunk(0);

    for (int kk = 0; kk < 12; kk++) {
        if (kk + 1 < 12) { load_chunk(kk + 1); CP_WAIT(1); }
        else             { CP_WAIT(0); }
        __syncthreads();

        const uint32_t* Aw = (const uint32_t*)(smem + (kk & 1) * STAGE);
        const uint32_t* Bw = (const uint32_t*)(smem + (kk & 1) * STAGE + ST_A);

        #pragma unroll
        for (int s = 0; s < 4; s++) {
            uint32_t afr[4][4];
            #pragma unroll
            for (int mf = 0; mf < 4; mf++) {
                int r = wm * 64 + mf * 16 + g;
                afr[mf][0] = Aw[(r    ) * WPITCH + s*8     + t];
                afr[mf][1] = Aw[(r + 8) * WPITCH + s*8     + t];
                afr[mf][2] = Aw[(r    ) * WPITCH + s*8 + 4 + t];
                afr[mf][3] = Aw[(r + 8) * WPITCH + s*8 + 4 + t];
            }
            uint32_t bfr[4][2];
            #pragma unroll
            for (int nf = 0; nf < 4; nf++) {
                int r = wn * 32 + nf * 8 + g;
                bfr[nf][0] = Bw[r * WPITCH + s*8     + t];
                bfr[nf][1] = Bw[r * WPITCH + s*8 + 4 + t];
            }
            #pragma unroll
            for (int mf = 0; mf < 4; mf++)
                #pragma unroll
                for (int nf = 0; nf < 4; nf++)
                    mma16816(acc[mf][nf], afr[mf], bfr[nf]);
        }
        __syncthreads();
    }

    #pragma unroll
    for (int mf = 0; mf < 4; mf++) {
        int o  = o0 + wm * 64 + mf * 16 + g;
        float bv0 = bias[o];
        float bv1 = bias[o + 8];
        float* r0 = out + ((size_t)b * C_ + o    ) * HW_;
        float* r1 = out + ((size_t)b * C_ + o + 8) * HW_;
        #pragma unroll
        for (int nf = 0; nf < 4; nf++) {
            int p = p0 + wn * 32 + nf * 8 + 2 * t;
            if (p < HW_) {
                *(float2*)(r0 + p) = make_float2(acc[mf][nf][0] + bv0, acc[mf][nf][1] + bv0);
                *(float2*)(r1 + p) = make_float2(acc[mf][nf][2] + bv1, acc[mf][nf][3] + bv1);
            }
        }
    }
}

// ---------------------------------------------------------------------------
extern "C" void kernel_launch(void* const* d_in, const int* in_sizes, int n_in,
                              void* d_out, int out_size) {
    const float* feat   = (const float*)d_in[0];
    const float* nearby = (const float*)d_in[1];
    const float* wf     = (const float*)d_in[2];
    const float* bf     = (const float*)d_in[3];
    float* out = (float*)d_out;

    cudaFuncSetAttribute(gemm_kernel, cudaFuncAttributeMaxDynamicSharedMemorySize, GEMM_SMEM);

    wprep_kernel<<<C_*C_/256, 256>>>(wf);
    zero_mism<<<(B_*N_*HW_ + 255)/256, 256>>>();

    dim3 g1((HW_ + 255) / 256, B_ * (N_ + 1));
    sum_kernel<<<g1, 256>>>(feat, nearby);
    avg_kernel<<<g1, 256>>>();

    dim3 g3((W_ + TW - 1) / TW, (H_ + TH - 1) / TH, B_ * 8);
    sim_kernel<<<g3, 256>>>(feat, nearby);

    dim3 g4(HW_ / 32, B_);
    fuse_kernel<<<g4, 256>>>(feat, nearby);

    dim3 g5(PPAD / 128, C_ / 128, B_);
    gemm_kernel<<<g5, 256, GEMM_SMEM>>>(bf, out);
}

// round 13
// speedup vs baseline: 1.8991x; 1.0398x over previous
#include <cuda_runtime.h>
#include <cuda_bf16.h>
#include <stdint.h>
#include <math.h>

#define B_ 4
#define N_ 4
#define C_ 256
#define H_ 100
#define W_ 152
#define HW_ (H_*W_)
#define PPAD 15360           // 120 tiles of 128 px

// ---------------- device scratch (no allocations allowed) ----------------
__device__ float g_S   [B_*(N_+1)*HW_];
__device__ float g_avg [B_*(N_+1)*HW_];
__device__ int   g_mism[B_*N_*HW_];
__device__ __nv_bfloat16 g_whi[C_*C_];
__device__ __nv_bfloat16 g_wlo[C_*C_];
__device__ __nv_bfloat16 g_fhiT[(size_t)B_*PPAD*C_];   // fused^T hi [b][p][c]
__device__ __nv_bfloat16 g_floT[(size_t)B_*PPAD*C_];   // fused^T lo [b][p][c]

__device__ __forceinline__ uint32_t smem_u32(const void* p) {
    uint32_t a;
    asm("{ .reg .u64 t; cvta.to.shared.u64 t, %1; cvt.u32.u64 %0, t; }" : "=r"(a) : "l"(p));
    return a;
}
#define CP_ASYNC16(dst, src) \
    asm volatile("cp.async.cg.shared.global [%0], [%1], 16;" :: "r"(dst), "l"(src))
#define CP_COMMIT() asm volatile("cp.async.commit_group;" ::: "memory")
#define CP_WAIT(n)  asm volatile("cp.async.wait_group %0;" :: "n"(n) : "memory")

__device__ __forceinline__ void mma16816(float* d, const uint32_t* a, const uint32_t* b) {
    asm volatile("mma.sync.aligned.m16n8k16.row.col.f32.bf16.bf16.f32 "
        "{%0,%1,%2,%3}, {%4,%5,%6,%7}, {%8,%9}, {%0,%1,%2,%3};"
        : "+f"(d[0]), "+f"(d[1]), "+f"(d[2]), "+f"(d[3])
        : "r"(a[0]), "r"(a[1]), "r"(a[2]), "r"(a[3]), "r"(b[0]), "r"(b[1]));
}

// Explicit PRMT (default mode): selector nibble bit 3 = sign-replicate the
// selected byte's MSB across the output byte (PTX ISA documented). The
// __byte_perm intrinsic may mask this mode bit — hence raw asm.
__device__ __forceinline__ int prmt_sign2(unsigned a, unsigned b) {
    unsigned r;
    asm("prmt.b32 %0, %1, %2, 0x00FB;" : "=r"(r) : "r"(a), "r"(b));
    return (int)r;   // byte0 = 0xFF if sign(a), byte1 = 0xFF if sign(b), bytes2,3 ignored
}
__device__ __forceinline__ int prmt_sign1(unsigned a) {
    unsigned r;
    asm("prmt.b32 %0, %1, %1, 0x000B;" : "=r"(r) : "r"(a));
    return (int)r;   // byte0 = 0xFF if sign(a)
}

// ---------------------------------------------------------------------------
// K0: split W into bf16 hi/lo
// ---------------------------------------------------------------------------
__global__ __launch_bounds__(256) void wprep_kernel(const float* __restrict__ w) {
    int i = blockIdx.x * 256 + threadIdx.x;
    float v = w[i];
    __nv_bfloat16 hi = __float2bfloat16(v);
    g_whi[i] = hi;
    g_wlo[i] = __float2bfloat16(v - __bfloat162float(hi));
}

// zero mismatch accumulators (graph replays must be deterministic)
__global__ __launch_bounds__(256) void zero_mism() {
    int i = blockIdx.x * 256 + threadIdx.x;
    if (i < B_*N_*HW_) g_mism[i] = 0;
}

// ---------------------------------------------------------------------------
// K1: per-pixel channel sum, sequential ascending c (bit-exact association)
// ---------------------------------------------------------------------------
__global__ __launch_bounds__(256) void sum_kernel(const float* __restrict__ feat,
                                                  const float* __restrict__ nearby) {
    int p = blockIdx.x * blockDim.x + threadIdx.x;
    int m = blockIdx.y;
    if (p >= HW_) return;
    int b = m / (N_+1), t = m % (N_+1);
    const float* src = (t == 0) ? (feat + (size_t)b * C_ * HW_)
                                : (nearby + (size_t)(b * N_ + (t-1)) * C_ * HW_);
    float acc = 0.0f;
    #pragma unroll 1
    for (int c0 = 0; c0 < C_; c0 += 8) {
        float v[8];
        #pragma unroll
        for (int k = 0; k < 8; k++) v[k] = src[(size_t)(c0 + k) * HW_ + p];
        #pragma unroll
        for (int k = 0; k < 8; k++) acc += v[k];
    }
    g_S[(size_t)m * HW_ + p] = acc;
}

// ---------------------------------------------------------------------------
// K2: 3x3 edge-clamped box average, (di,dj) row-major add order
// ---------------------------------------------------------------------------
__global__ __launch_bounds__(256) void avg_kernel() {
    int p = blockIdx.x * blockDim.x + threadIdx.x;
    int m = blockIdx.y;
    if (p >= HW_) return;
    int i = p / W_, j = p % W_;
    const float* S = g_S + (size_t)m * HW_;
    float acc = 0.0f;
    #pragma unroll
    for (int di = 0; di < 3; di++) {
        int y = min(max(i + di - 1, 0), H_ - 1);
        #pragma unroll
        for (int dj = 0; dj < 3; dj++) {
            int x = min(max(j + dj - 1, 0), W_ - 1);
            acc += S[y * W_ + x];
        }
    }
    g_avg[(size_t)m * HW_ + p] = acc * (1.0f / 2304.0f);
}

// ---------------------------------------------------------------------------
// K3: census mismatch counts via sign-XOR + PRMT(sign-replicate) + DP4A
// 2 px/thread (32x16 tile), 16B cp.async rows, 3-slot ring, 1 bar/chan
// ---------------------------------------------------------------------------
#define TW 32
#define TH 16
#define SROW 40                        // floats per smem row (aligned 160B)
#define PROWS 18                       // halo rows per plane
#define PLANEF (PROWS*SROW)            // 720
#define CHF (5*PLANEF)                 // 3600 floats per channel
#define LOADS (5*PROWS*10)             // 900 uint4 per channel
#define CHUNK 32

__global__ __launch_bounds__(256, 3) void sim_kernel(const float* __restrict__ feat,
                                                     const float* __restrict__ nearby) {
    __shared__ float sm[3][CHF];       // 43.2 KB triple-buffer ring

    int tid = threadIdx.x;
    int tx = tid & 31;
    int ty = tid >> 5;                 // 0..7
    int j0 = blockIdx.x * TW, i0 = blockIdx.y * TH;
    int bz = blockIdx.z;
    int b  = bz >> 3;
    int c0 = (bz & 7) * CHUNK;
    int iA = i0 + 2*ty, iB = iA + 1;
    int j  = j0 + tx;
    bool vA = (iA < H_) && (j < W_);
    bool vB = (iB < H_) && (j < W_);
    int pA = iA * W_ + j, pB = pA + W_;

    int xlo = max(j0 - 4, 0);
    // smem x-indices for dx = 0,1,2 (edge-clamped like the reference)
    int sx0 = min(max(j - 1, 0), W_-1) - xlo;
    int sx1 = min(max(j    , 0), W_-1) - xlo;
    int sx2 = min(max(j + 1, 0), W_-1) - xlo;

    float T1a = 0.f, T1b = 0.f, T2a[N_] = {0,0,0,0}, T2b[N_] = {0,0,0,0};
    if (vA) {
        T1a = g_avg[(size_t)(b*5 + 0) * HW_ + pA];
        #pragma unroll
        for (int n = 0; n < N_; n++) T2a[n] = g_avg[(size_t)(b*5 + 1 + n) * HW_ + pA];
    }
    if (vB) {
        T1b = g_avg[(size_t)(b*5 + 0) * HW_ + pB];
        #pragma unroll
        for (int n = 0; n < N_; n++) T2b[n] = g_avg[(size_t)(b*5 + 1 + n) * HW_ + pB];
    }

    // cooperative loader: 900 uint4 per channel, 4 slots/thread
    const float* fbase = feat   + ((size_t)b * C_ + c0) * HW_;
    const float* nbase = nearby + ((size_t)(b * N_) * C_ + c0) * HW_;
    const float* lptr[4];
    uint32_t sdst[4];
    uint32_t smbase = smem_u32(&sm[0][0]);
    #pragma unroll
    for (int q = 0; q < 4; q++) {
        int idx = tid + q * 256;
        if (idx < LOADS) {
            int row = idx / 10, ch = idx % 10;
            int t = row / PROWS, r = row % PROWS;
            int gy = min(max(i0 + r - 1, 0), H_ - 1);
            int xs = min(xlo + ch * 4, W_ - 4);      // stay in-plane; extra slots unused
            const float* base = (t == 0) ? fbase : (nbase + (size_t)(t - 1) * C_ * HW_);
            lptr[q] = base + gy * W_ + xs;
            sdst[q] = smbase + (uint32_t)(t * PLANEF + r * SROW + ch * 4) * 4u;
        } else {
            lptr[q] = fbase;   // idx 768..899 only in q=3; guard below
            sdst[q] = smbase;
        }
    }
    bool q3 = (tid + 3*256) < LOADS;

    // prefetch channels 0 and 1 into slots 0 and 1
    #pragma unroll
    for (int s = 0; s < 2; s++) {
        uint32_t soff = (uint32_t)s * (CHF * 4u);
        size_t goff = (size_t)s * HW_;
        #pragma unroll
        for (int q = 0; q < 3; q++) CP_ASYNC16(sdst[q] + soff, lptr[q] + goff);
        if (q3) CP_ASYNC16(sdst[3] + soff, lptr[3] + goff);
        CP_COMMIT();
    }

    // mA/mB accumulate NEGATIVE mismatch counts via signed dp4a
    int mA[N_] = {0,0,0,0}, mB[N_] = {0,0,0,0};

    #pragma unroll 1
    for (int c = 0; c < CHUNK; c++) {
        CP_WAIT(1);                    // group c arrived (c+1 may be in flight)
        __syncthreads();               // all threads past compute of c-1 -> slot (c+2)%3 free

        if (c + 2 < CHUNK) {           // prefetch c+2 into the freed slot
            uint32_t soff = (uint32_t)((c + 2) % 3) * (CHF * 4u);
            size_t goff = (size_t)(c + 2) * HW_;
            #pragma unroll
            for (int q = 0; q < 3; q++) CP_ASYNC16(sdst[q] + soff, lptr[q] + goff);
            if (q3) CP_ASYNC16(sdst[3] + soff, lptr[3] + goff);
        }
        CP_COMMIT();                   // empty tail groups keep wait counts aligned

        const float* S = &sm[c % 3][0] + (2 * ty) * SROW;

        // feature plane: sign words for both pixels
        unsigned uA[9], uB[9];
        {
            float x[4][3];
            #pragma unroll
            for (int rr = 0; rr < 4; rr++) {
                x[rr][0] = S[rr * SROW + sx0];
                x[rr][1] = S[rr * SROW + sx1];
                x[rr][2] = S[rr * SROW + sx2];
            }
            #pragma unroll
            for (int dy = 0; dy < 3; dy++)
                #pragma unroll
                for (int dx = 0; dx < 3; dx++) {
                    uA[dy*3+dx] = __float_as_uint(x[dy  ][dx] - T1a);
                    uB[dy*3+dx] = __float_as_uint(x[dy+1][dx] - T1b);
                }
        }
        #pragma unroll
        for (int n = 0; n < N_; n++) {
            const float* Sn = S + (1 + n) * PLANEF;
            float x[4][3];
            #pragma unroll
            for (int rr = 0; rr < 4; rr++) {
                x[rr][0] = Sn[rr * SROW + sx0];
                x[rr][1] = Sn[rr * SROW + sx1];
                x[rr][2] = Sn[rr * SROW + sx2];
            }
            unsigned xA[9], xB[9];
            #pragma unroll
            for (int dy = 0; dy < 3; dy++)
                #pragma unroll
                for (int dx = 0; dx < 3; dx++) {
                    int k = dy*3 + dx;
                    xA[k] = uA[k] ^ __float_as_uint(x[dy  ][dx] - T2a[n]);
                    xB[k] = uB[k] ^ __float_as_uint(x[dy+1][dx] - T2b[n]);
                }
            // prmt sign-replicate packs two sign bytes (0x00 / 0xFF);
            // dp4a with 0x0101 adds -1 per mismatch (signed bytes).
            #pragma unroll
            for (int i = 0; i < 4; i++) {
                mA[n] = __dp4a(prmt_sign2(xA[2*i], xA[2*i+1]), 0x00000101, mA[n]);
                mB[n] = __dp4a(prmt_sign2(xB[2*i], xB[2*i+1]), 0x00000101, mB[n]);
            }
            mA[n] = __dp4a(prmt_sign1(xA[8]), 0x00000001, mA[n]);
            mB[n] = __dp4a(prmt_sign1(xB[8]), 0x00000001, mB[n]);
        }
    }

    if (vA) {
        #pragma unroll
        for (int n = 0; n < N_; n++)
            atomicAdd(&g_mism[(size_t)(b * N_ + n) * HW_ + pA], -mA[n]);
    }
    if (vB) {
        #pragma unroll
        for (int n = 0; n < N_; n++)
            atomicAdd(&g_mism[(size_t)(b * N_ + n) * HW_ + pB], -mB[n]);
    }
}

// ---------------------------------------------------------------------------
// K4: softmax + weighted fuse; writes bf16 hi/lo TRANSPOSED [b][p][c]
// ---------------------------------------------------------------------------
__global__ __launch_bounds__(256) void fuse_kernel(const float* __restrict__ feat,
                                                   const float* __restrict__ nearby) {
    __shared__ float4 w_s[32];
    __shared__ __nv_bfloat16 s_hi[32][258];
    __shared__ __nv_bfloat16 s_lo[32][258];

    int tid = threadIdx.x;
    int b = blockIdx.y;
    int p0 = blockIdx.x * 32;

    if (tid < 32) {
        int p = p0 + tid;
        int m0 = g_mism[(size_t)(b*N_+0)*HW_ + p];
        int m1 = g_mism[(size_t)(b*N_+1)*HW_ + p];
        int m2 = g_mism[(size_t)(b*N_+2)*HW_ + p];
        int m3 = g_mism[(size_t)(b*N_+3)*HW_ + p];
        int mn = min(min(m0, m1), min(m2, m3));
        float e0 = expf((float)(mn - m0));
        float e1 = expf((float)(mn - m1));
        float e2 = expf((float)(mn - m2));
        float e3 = expf((float)(mn - m3));
        float s = e0 + e1 + e2 + e3;
        w_s[tid] = make_float4(e0 / s, e1 / s, e2 / s, e3 / s);
    }
    __syncthreads();

    int c   = tid >> 3;
    int px0 = (tid & 7) * 4;
    const float* fp = feat   + (size_t)b * C_ * HW_ + p0 + px0;
    const float* np = nearby + (size_t)b * N_ * C_ * HW_ + p0 + px0;
    float4 wv[4] = {w_s[px0], w_s[px0+1], w_s[px0+2], w_s[px0+3]};

    #pragma unroll
    for (int cc = 0; cc < 8; cc++) {
        int cg = cc * 32 + c;
        size_t co = (size_t)cg * HW_;
        float4 fv = *(const float4*)(fp + co);
        float4 a0 = *(const float4*)(np + co);
        float4 a1 = *(const float4*)(np + (size_t)C_ * HW_ + co);
        float4 a2 = *(const float4*)(np + (size_t)2 * C_ * HW_ + co);
        float4 a3 = *(const float4*)(np + (size_t)3 * C_ * HW_ + co);
        float fr[4] = {fv.x, fv.y, fv.z, fv.w};
        float r0[4] = {a0.x, a0.y, a0.z, a0.w};
        float r1[4] = {a1.x, a1.y, a1.z, a1.w};
        float r2[4] = {a2.x, a2.y, a2.z, a2.w};
        float r3[4] = {a3.x, a3.y, a3.z, a3.w};
        #pragma unroll
        for (int e = 0; e < 4; e++) {
            float4 w = wv[e];
            float v = w.x * r0[e];
            v = fmaf(w.y, r1[e], v);
            v = fmaf(w.z, r2[e], v);
            v = fmaf(w.w, r3[e], v);
            v += fr[e];
            __nv_bfloat16 hi = __float2bfloat16(v);
            s_hi[px0 + e][cg] = hi;
            s_lo[px0 + e][cg] = __float2bfloat16(v - __bfloat162float(hi));
        }
    }
    __syncthreads();

    uint32_t* dh = (uint32_t*)g_fhiT + ((size_t)b * PPAD + p0) * (C_/2);
    uint32_t* dl = (uint32_t*)g_floT + ((size_t)b * PPAD + p0) * (C_/2);
    #pragma unroll
    for (int q = 0; q < 16; q++) {
        int w = tid + q * 256;
        int row = w >> 7, cw = w & 127;
        dh[(size_t)row * 128 + cw] = *(const uint32_t*)&s_hi[row][cw * 2];
        dl[(size_t)row * 128 + cw] = *(const uint32_t*)&s_lo[row][cw * 2];
    }
}

// ---------------------------------------------------------------------------
// K5: mma.sync bf16 split GEMM.  out[b][o][p] = sum_c W[o][c]*F[c][p] + bias[o]
// ---------------------------------------------------------------------------
#define WPITCH 36                       // 32-bit words per smem row
#define ST_A   18432                    // 128*144 bytes
#define STAGE  36864                    // A + B per stage
#define GEMM_SMEM (2*STAGE)             // 73728

__global__ __launch_bounds__(256, 2)
void gemm_kernel(const float* __restrict__ bias, float* __restrict__ out) {
    extern __shared__ char smem[];
    uint32_t sb = smem_u32(smem);

    int tid = threadIdx.x, wid = tid >> 5, lid = tid & 31;
    int g = lid >> 2, t = lid & 3;
    int wm = wid & 1, wn = wid >> 1;
    int p0 = blockIdx.x * 128, o0 = blockIdx.y * 128, b = blockIdx.z;

    int ldrow = tid >> 3, ldcol = tid & 7;

    float acc[4][4][4];
    #pragma unroll
    for (int i = 0; i < 4; i++)
        #pragma unroll
        for (int j = 0; j < 4; j++)
            #pragma unroll
            for (int k = 0; k < 4; k++) acc[i][j][k] = 0.0f;

    auto load_chunk = [&](int kk) {
        int buf = kk & 1, seg = kk >> 2, cc0 = (kk & 3) * 64;
        const __nv_bfloat16* As = (seg < 2) ? g_whi : g_wlo;
        const __nv_bfloat16* Bs = (seg == 1) ? g_floT : g_fhiT;
        uint32_t da = sb + buf * STAGE;
        uint32_t db = da + ST_A;
        const __nv_bfloat16* ga = As + (size_t)(o0 + ldrow) * C_ + cc0 + ldcol * 8;
        const __nv_bfloat16* gb = Bs + ((size_t)b * PPAD + p0 + ldrow) * C_ + cc0 + ldcol * 8;
        #pragma unroll
        for (int q = 0; q < 4; q++) {
            CP_ASYNC16(da + (ldrow + q*32) * 144 + ldcol * 16, ga + (size_t)(q*32) * C_);
            CP_ASYNC16(db + (ldrow + q*32) * 144 + ldcol * 16, gb + (size_t)(q*32) * C_);
        }
        CP_COMMIT();
    };

    load_chunk(0);

    for (int kk = 0; kk < 12; kk++) {
        if (kk + 1 < 12) { load_chunk(kk + 1); CP_WAIT(1); }
        else             { CP_WAIT(0); }
        __syncthreads();

        const uint32_t* Aw = (const uint32_t*)(smem + (kk & 1) * STAGE);
        const uint32_t* Bw = (const uint32_t*)(smem + (kk & 1) * STAGE + ST_A);

        #pragma unroll
        for (int s = 0; s < 4; s++) {
            uint32_t afr[4][4];
            #pragma unroll
            for (int mf = 0; mf < 4; mf++) {
                int r = wm * 64 + mf * 16 + g;
                afr[mf][0] = Aw[(r    ) * WPITCH + s*8     + t];
                afr[mf][1] = Aw[(r + 8) * WPITCH + s*8     + t];
                afr[mf][2] = Aw[(r    ) * WPITCH + s*8 + 4 + t];
                afr[mf][3] = Aw[(r + 8) * WPITCH + s*8 + 4 + t];
            }
            uint32_t bfr[4][2];
            #pragma unroll
            for (int nf = 0; nf < 4; nf++) {
                int r = wn * 32 + nf * 8 + g;
                bfr[nf][0] = Bw[r * WPITCH + s*8     + t];
                bfr[nf][1] = Bw[r * WPITCH + s*8 + 4 + t];
            }
            #pragma unroll
            for (int mf = 0; mf < 4; mf++)
                #pragma unroll
                for (int nf = 0; nf < 4; nf++)
                    mma16816(acc[mf][nf], afr[mf], bfr[nf]);
        }
        __syncthreads();
    }

    #pragma unroll
    for (int mf = 0; mf < 4; mf++) {
        int o  = o0 + wm * 64 + mf * 16 + g;
        float bv0 = bias[o];
        float bv1 = bias[o + 8];
        float* r0 = out + ((size_t)b * C_ + o    ) * HW_;
        float* r1 = out + ((size_t)b * C_ + o + 8) * HW_;
        #pragma unroll
        for (int nf = 0; nf < 4; nf++) {
            int p = p0 + wn * 32 + nf * 8 + 2 * t;
            if (p < HW_) {
                *(float2*)(r0 + p) = make_float2(acc[mf][nf][0] + bv0, acc[mf][nf][1] + bv0);
                *(float2*)(r1 + p) = make_float2(acc[mf][nf][2] + bv1, acc[mf][nf][3] + bv1);
            }
        }
    }
}

// ---------------------------------------------------------------------------
extern "C" void kernel_launch(void* const* d_in, const int* in_sizes, int n_in,
                              void* d_out, int out_size) {
    const float* feat   = (const float*)d_in[0];
    const float* nearby = (const float*)d_in[1];
    const float* wf     = (const float*)d_in[2];
    const float* bf     = (const float*)d_in[3];
    float* out = (float*)d_out;

    cudaFuncSetAttribute(gemm_kernel, cudaFuncAttributeMaxDynamicSharedMemorySize, GEMM_SMEM);

    wprep_kernel<<<C_*C_/256, 256>>>(wf);
    zero_mism<<<(B_*N_*HW_ + 255)/256, 256>>>();

    dim3 g1((HW_ + 255) / 256, B_ * (N_ + 1));
    sum_kernel<<<g1, 256>>>(feat, nearby);
    avg_kernel<<<g1, 256>>>();

    dim3 g3((W_ + TW - 1) / TW, (H_ + TH - 1) / TH, B_ * 8);
    sim_kernel<<<g3, 256>>>(feat, nearby);

    dim3 g4(HW_ / 32, B_);
    fuse_kernel<<<g4, 256>>>(feat, nearby);

    dim3 g5(PPAD / 128, C_ / 128, B_);
    gemm_kernel<<<g5, 256, GEMM_SMEM>>>(bf, out);
}